// round 11
// baseline (speedup 1.0000x reference)
#include <cuda_runtime.h>
#include <cuda_fp16.h>

#define NN 50000
#define EE 800000
#define NB_SCAN 49    // ceil(50000/1024)
#define GB1 391       // ceil(50000/128) gemm row-tiles
#define EB2 1563      // ceil(400000/256) edge-pair blocks

// ---------------- scratch ----------------
__device__ int   g_is64;
__device__ int   g_flag;           // scan sync counter (reset each replay)
__device__ int   g_cnt[NN];
__device__ int   g_fill[NN];
__device__ int   g_rowptr[NN + 1];
__device__ int   g_col[EE];
__device__ int   g_bsum[64];
__device__ __align__(16) float  g_dinv[NN];
__device__ __align__(16) __half g_h1h[NN * 128];   // x @ W1, fp16
__device__ __align__(16) float  g_hb[NN * 128];    // relu(agg1 + b1), fp32
__device__ __align__(16) __half g_t2h[NN * 64];    // hb @ W2, fp16

#define FMA_F32X2(d, a, b, c) \
    asm("fma.rn.f32x2 %0, %1, %2, %3;" : "=l"(d) : "l"(a), "l"(b), "l"(c))
#define PACK_DUP(out, w) \
    asm("mov.b64 %0, {%1, %2};" : "=l"(out) : "f"(w), "f"(w))

__device__ __forceinline__ int clampn(int v) {
    if (v < 0) v = 0;
    if (v >= NN) v = NN - 1;
    return v;
}

// ---------------- init: zero counters + flag + dtype sniff ----------------
__global__ void k_init(const unsigned* __restrict__ w) {
    int i = blockIdx.x * blockDim.x + threadIdx.x;
    if (i < NN) { g_cnt[i] = 0; g_fill[i] = 0; }
    if (i == 0) {
        g_flag = 0;
        int all0 = 1;
        for (int k = 0; k < 64; k++)
            if (w[2 * k + 1] != 0u) { all0 = 0; break; }
        g_is64 = all0;
    }
}

// ---------------- GEMM body (fp16 out) ----------------
template <int CO, int XSEL>
__device__ __forceinline__ void gemm_body(const float* __restrict__ Xext,
                                          const float* __restrict__ W,
                                          __half* __restrict__ H16,
                                          int row0, int c0) {
    const float* X = (XSEL == 0) ? Xext : g_hb;

    __shared__ float Xt[32][130];
    __shared__ __align__(16) float Ws[32][64];

    int tid = threadIdx.x;
    int tx  = tid & 15;
    int ty  = tid >> 4;

    unsigned long long acc[4][4];
    #pragma unroll
    for (int p = 0; p < 4; p++)
        #pragma unroll
        for (int c = 0; c < 4; c++) acc[p][c] = 0ull;

    for (int ch = 0; ch < 4; ch++) {
        #pragma unroll
        for (int it = 0; it < 4; it++) {
            int idx = it * 256 + tid;
            int cc2 = idx & 31;
            int jj  = idx >> 5;
            *(float2*)&Ws[jj][cc2 * 2] =
                *(const float2*)(W + (size_t)(ch * 32 + jj) * CO + c0 + cc2 * 2);
        }
        #pragma unroll
        for (int it = 0; it < 4; it++) {
            int idx = it * 256 + tid;
            int j4  = idx & 7;
            int r   = idx >> 3;
            float4 v = make_float4(0.f, 0.f, 0.f, 0.f);
            if (row0 + r < NN)
                v = *(const float4*)(X + (size_t)(row0 + r) * 128 + ch * 32 + j4 * 4);
            Xt[j4 * 4 + 0][r] = v.x;
            Xt[j4 * 4 + 1][r] = v.y;
            Xt[j4 * 4 + 2][r] = v.z;
            Xt[j4 * 4 + 3][r] = v.w;
        }
        __syncthreads();

        #pragma unroll
        for (int jj = 0; jj < 32; jj++) {
            unsigned long long a[4];
            #pragma unroll
            for (int p = 0; p < 4; p++)
                a[p] = *(const unsigned long long*)&Xt[jj][ty * 8 + p * 2];
            float4 wv = *(const float4*)&Ws[jj][tx * 4];
            unsigned long long wb[4];
            PACK_DUP(wb[0], wv.x);
            PACK_DUP(wb[1], wv.y);
            PACK_DUP(wb[2], wv.z);
            PACK_DUP(wb[3], wv.w);
            #pragma unroll
            for (int c = 0; c < 4; c++)
                #pragma unroll
                for (int p = 0; p < 4; p++)
                    FMA_F32X2(acc[p][c], a[p], wb[c], acc[p][c]);
        }
        __syncthreads();
    }

    #pragma unroll
    for (int p = 0; p < 4; p++) {
        int r = row0 + ty * 8 + p * 2;
        float4 lo, hi;
        float* lop = &lo.x; float* hip = &hi.x;
        #pragma unroll
        for (int c = 0; c < 4; c++) {
            lop[c] = __uint_as_float((unsigned)(acc[p][c] & 0xffffffffull));
            hip[c] = __uint_as_float((unsigned)(acc[p][c] >> 32));
        }
        __half2 l01 = __floats2half2_rn(lo.x, lo.y);
        __half2 l23 = __floats2half2_rn(lo.z, lo.w);
        __half2 h01 = __floats2half2_rn(hi.x, hi.y);
        __half2 h23 = __floats2half2_rn(hi.z, hi.w);
        if (r < NN) {
            uint2 v; v.x = *(unsigned*)&l01; v.y = *(unsigned*)&l23;
            *(uint2*)(H16 + (size_t)r * CO + c0 + tx * 4) = v;
        }
        if (r + 1 < NN) {
            uint2 v; v.x = *(unsigned*)&h01; v.y = *(unsigned*)&h23;
            *(uint2*)(H16 + (size_t)(r + 1) * CO + c0 + tx * 4) = v;
        }
    }
}

// ---------------- fused A: GEMM1 cols 0-63 || edge count ----------------
__global__ __launch_bounds__(256) void k_fusedA(const float* __restrict__ x,
                                                const float* __restrict__ W1,
                                                const void* __restrict__ ei) {
    if (blockIdx.x < GB1) {
        gemm_body<128, 0>(x, W1, g_h1h, blockIdx.x * 128, 0);
    } else {
        int idx = (blockIdx.x - GB1) * 256 + threadIdx.x;
        if (idx < EE / 2) {
            int d0, d1;
            if (g_is64) {
                ulonglong2 p = ((const ulonglong2*)((const char*)ei + (size_t)EE * 8))[idx];
                d0 = clampn((int)p.x); d1 = clampn((int)p.y);
            } else {
                int2 p = ((const int2*)((const char*)ei + (size_t)EE * 4))[idx];
                d0 = clampn(p.x); d1 = clampn(p.y);
            }
            atomicAdd(&g_cnt[d0], 1);
            atomicAdd(&g_cnt[d1], 1);
        }
    }
}

// ---------------- merged scan: block sums + publish/spin + rowptr + dinv ----------------
__global__ __launch_bounds__(1024) void k_scan49() {
    __shared__ int sh[1024];
    __shared__ int sb[64];
    __shared__ int s_boff;
    int t = threadIdx.x;
    int i = blockIdx.x * 1024 + t;
    int c = (i < NN) ? g_cnt[i] : 0;

    // block-local inclusive scan
    sh[t] = c;
    __syncthreads();
    #pragma unroll
    for (int off = 1; off < 1024; off <<= 1) {
        int u = (t >= off) ? sh[t - off] : 0;
        __syncthreads();
        sh[t] += u;
        __syncthreads();
    }

    // publish block sum, then wait for all blocks
    if (t == 1023) {
        g_bsum[blockIdx.x] = sh[1023];
        __threadfence();
        atomicAdd(&g_flag, 1);
    }
    if (t == 0) {
        while (*(volatile int*)&g_flag < NB_SCAN) { }
    }
    __syncthreads();

    // scan the 49 block sums locally
    if (t < 64) sb[t] = (t < NB_SCAN) ? *(volatile int*)&g_bsum[t] : 0;
    __syncthreads();
    #pragma unroll
    for (int off = 1; off < 64; off <<= 1) {
        int u = (t < 64 && t >= off) ? sb[t - off] : 0;
        __syncthreads();
        if (t < 64) sb[t] += u;
        __syncthreads();
    }
    if (t == 0) s_boff = (blockIdx.x == 0) ? 0 : sb[blockIdx.x - 1];
    __syncthreads();

    if (i < NN) {
        g_rowptr[i] = sh[t] - c + s_boff;
        g_dinv[i]   = rsqrtf((float)(c + 1));
    }
    if (i == 0) g_rowptr[NN] = EE;
}

// ---------------- fused B: GEMM1 cols 64-127 || edge scatter ----------------
__global__ __launch_bounds__(256) void k_fusedB(const float* __restrict__ x,
                                                const float* __restrict__ W1,
                                                const void* __restrict__ ei) {
    if (blockIdx.x < GB1) {
        gemm_body<128, 0>(x, W1, g_h1h, blockIdx.x * 128, 64);
    } else {
        int idx = (blockIdx.x - GB1) * 256 + threadIdx.x;
        if (idx < EE / 2) {
            int s0, s1, d0, d1;
            if (g_is64) {
                ulonglong2 ps = ((const ulonglong2*)ei)[idx];
                ulonglong2 pd = ((const ulonglong2*)((const char*)ei + (size_t)EE * 8))[idx];
                s0 = clampn((int)ps.x); s1 = clampn((int)ps.y);
                d0 = clampn((int)pd.x); d1 = clampn((int)pd.y);
            } else {
                int2 ps = ((const int2*)ei)[idx];
                int2 pd = ((const int2*)((const char*)ei + (size_t)EE * 4))[idx];
                s0 = clampn(ps.x); s1 = clampn(ps.y);
                d0 = clampn(pd.x); d1 = clampn(pd.y);
            }
            int p0 = g_rowptr[d0] + atomicAdd(&g_fill[d0], 1);
            g_col[p0] = s0;
            int p1 = g_rowptr[d1] + atomicAdd(&g_fill[d1], 1);
            g_col[p1] = s1;
        }
    }
}

// ---------------- standalone GEMM (layer 2) ----------------
__global__ __launch_bounds__(256) void k_gemm2(const float* __restrict__ W) {
    gemm_body<64, 1>(nullptr, W, g_t2h, blockIdx.x * 128, 0);
}

// ---------------- agg helpers: partial neighbor sum over [jb, je) ----------------
__device__ __forceinline__ void agg_range_128(int jb, int je, int lane, float di,
                                              float& a0, float& a1, float& a2, float& a3) {
    int j = jb;
    for (; j + 4 <= je; j += 4) {
        int   si[4];
        float ni[4];
        #pragma unroll
        for (int q = 0; q < 4; q++) si[q] = g_col[j + q];
        #pragma unroll
        for (int q = 0; q < 4; q++) ni[q] = g_dinv[si[q]] * di;
        uint2 rv[4];
        #pragma unroll
        for (int q = 0; q < 4; q++)
            rv[q] = *(const uint2*)(g_h1h + (size_t)si[q] * 128 + lane * 4);
        #pragma unroll
        for (int q = 0; q < 4; q++) {
            float2 fa = __half22float2(*(__half2*)&rv[q].x);
            float2 fb = __half22float2(*(__half2*)&rv[q].y);
            a0 += fa.x * ni[q]; a1 += fa.y * ni[q];
            a2 += fb.x * ni[q]; a3 += fb.y * ni[q];
        }
    }
    for (; j < je; j++) {
        int   s   = g_col[j];
        float nrm = g_dinv[s] * di;
        uint2 raw = *(const uint2*)(g_h1h + (size_t)s * 128 + lane * 4);
        float2 fa = __half22float2(*(__half2*)&raw.x);
        float2 fb = __half22float2(*(__half2*)&raw.y);
        a0 += fa.x * nrm; a1 += fa.y * nrm; a2 += fb.x * nrm; a3 += fb.y * nrm;
    }
}

__device__ __forceinline__ void agg_range_64(int jb, int je, int lane, float di,
                                             float& a0, float& a1) {
    int j = jb;
    for (; j + 4 <= je; j += 4) {
        int   si[4];
        float ni[4];
        #pragma unroll
        for (int q = 0; q < 4; q++) si[q] = g_col[j + q];
        #pragma unroll
        for (int q = 0; q < 4; q++) ni[q] = g_dinv[si[q]] * di;
        unsigned rv[4];
        #pragma unroll
        for (int q = 0; q < 4; q++)
            rv[q] = *(const unsigned*)(g_t2h + (size_t)si[q] * 64 + lane * 2);
        #pragma unroll
        for (int q = 0; q < 4; q++) {
            float2 v = __half22float2(*(__half2*)&rv[q]);
            a0 += v.x * ni[q]; a1 += v.y * ni[q];
        }
    }
    for (; j < je; j++) {
        int   s   = g_col[j];
        float nrm = g_dinv[s] * di;
        unsigned raw = *(const unsigned*)(g_t2h + (size_t)s * 64 + lane * 2);
        float2 v = __half22float2(*(__half2*)&raw);
        a0 += v.x * nrm; a1 += v.y * nrm;
    }
}

// ---------------- agg layer 1: two warps per node (4 nodes / 256-thr block) ----------------
__global__ __launch_bounds__(256) void k_agg1(const float* __restrict__ bias) {
    __shared__ float part[4][128];
    int tid  = threadIdx.x;
    int wid  = tid >> 5;         // 0..7
    int lane = tid & 31;
    int nl   = wid >> 1;         // node slot in block, 0..3
    int half = wid & 1;
    int w    = blockIdx.x * 4 + nl;
    if (w >= NN) return;

    float di  = g_dinv[w];
    int   beg = g_rowptr[w];
    int   end = g_rowptr[w + 1];
    int   mid = beg + ((end - beg) >> 1);

    float a0 = 0.f, a1 = 0.f, a2 = 0.f, a3 = 0.f;
    if (half == 0) {
        float sn = di * di;                      // self loop
        uint2 raw = *(const uint2*)(g_h1h + (size_t)w * 128 + lane * 4);
        float2 fa = __half22float2(*(__half2*)&raw.x);
        float2 fb = __half22float2(*(__half2*)&raw.y);
        a0 = fa.x * sn; a1 = fa.y * sn; a2 = fb.x * sn; a3 = fb.y * sn;
        agg_range_128(beg, mid, lane, di, a0, a1, a2, a3);
    } else {
        agg_range_128(mid, end, lane, di, a0, a1, a2, a3);
        float4 pv = make_float4(a0, a1, a2, a3);
        *(float4*)&part[nl][lane * 4] = pv;
    }
    __syncthreads();

    if (half == 0) {
        float4 pv = *(float4*)&part[nl][lane * 4];
        float4 r;
        r.x = fmaxf(a0 + pv.x + bias[lane * 4 + 0], 0.f);
        r.y = fmaxf(a1 + pv.y + bias[lane * 4 + 1], 0.f);
        r.z = fmaxf(a2 + pv.z + bias[lane * 4 + 2], 0.f);
        r.w = fmaxf(a3 + pv.w + bias[lane * 4 + 3], 0.f);
        *(float4*)(g_hb + (size_t)w * 128 + lane * 4) = r;
    }
}

// ---------------- agg layer 2: two warps per node ----------------
__global__ __launch_bounds__(256) void k_agg2(const float* __restrict__ bias,
                                              float* __restrict__ out) {
    __shared__ float part[4][64];
    int tid  = threadIdx.x;
    int wid  = tid >> 5;
    int lane = tid & 31;
    int nl   = wid >> 1;
    int half = wid & 1;
    int w    = blockIdx.x * 4 + nl;
    if (w >= NN) return;

    float di  = g_dinv[w];
    int   beg = g_rowptr[w];
    int   end = g_rowptr[w + 1];
    int   mid = beg + ((end - beg) >> 1);

    float a0 = 0.f, a1 = 0.f;
    if (half == 0) {
        float sn = di * di;
        unsigned raw = *(const unsigned*)(g_t2h + (size_t)w * 64 + lane * 2);
        float2 v = __half22float2(*(__half2*)&raw);
        a0 = v.x * sn; a1 = v.y * sn;
        agg_range_64(beg, mid, lane, di, a0, a1);
    } else {
        agg_range_64(mid, end, lane, di, a0, a1);
        float2 pv = make_float2(a0, a1);
        *(float2*)&part[nl][lane * 2] = pv;
    }
    __syncthreads();

    if (half == 0) {
        float2 pv = *(float2*)&part[nl][lane * 2];
        float2 r;
        r.x = a0 + pv.x + bias[lane * 2 + 0];
        r.y = a1 + pv.y + bias[lane * 2 + 1];
        *(float2*)(out + (size_t)w * 64 + lane * 2) = r;
    }
}

// ---------------- launch ----------------
extern "C" void kernel_launch(void* const* d_in, const int* in_sizes, int n_in,
                              void* d_out, int out_size) {
    const float* x   = (const float*)d_in[0];
    const void*  ei  = d_in[1];
    const float* W1  = (const float*)d_in[2];
    const float* b1  = (const float*)d_in[3];
    const float* W2  = (const float*)d_in[4];
    const float* b2  = (const float*)d_in[5];
    float*       out = (float*)d_out;

    k_init<<<(NN + 255) / 256, 256>>>((const unsigned*)ei);
    k_fusedA<<<GB1 + EB2, 256>>>(x, W1, ei);   // gemm1 half0 || count
    k_scan49<<<NB_SCAN, 1024>>>();             // merged bsum + rowptr
    k_fusedB<<<GB1 + EB2, 256>>>(x, W1, ei);   // gemm1 half1 || scatter

    k_agg1<<<(NN + 3) / 4, 256>>>(b1);
    k_gemm2<<<GB1, 256>>>(W2);
    k_agg2<<<(NN + 3) / 4, 256>>>(b2, out);
}

// round 12
// speedup vs baseline: 1.1240x; 1.1240x over previous
#include <cuda_runtime.h>
#include <cuda_fp16.h>

#define NN 50000
#define EE 800000
#define NB_SCAN 49    // ceil(50000/1024)
#define GB1 391       // ceil(50000/128) gemm row-tiles
#define EB2 1563      // ceil(400000/256) edge-pair blocks

// ---------------- scratch ----------------
__device__ int   g_is64;
__device__ int   g_flag;           // scan sync counter (reset each replay)
__device__ int   g_cnt[NN];
__device__ int   g_fill[NN];
__device__ int   g_rowptr[NN + 1];
__device__ int   g_col[EE];
__device__ int   g_bsum[64];
__device__ __align__(16) float  g_dinv[NN];
__device__ __align__(16) __half g_h1h[NN * 128];   // x @ W1, fp16
__device__ __align__(16) float  g_hb[NN * 128];    // relu(agg1 + b1), fp32
__device__ __align__(16) __half g_t2h[NN * 64];    // hb @ W2, fp16

#define FMA_F32X2(d, a, b, c) \
    asm("fma.rn.f32x2 %0, %1, %2, %3;" : "=l"(d) : "l"(a), "l"(b), "l"(c))
#define PACK_DUP(out, w) \
    asm("mov.b64 %0, {%1, %2};" : "=l"(out) : "f"(w), "f"(w))

__device__ __forceinline__ int clampn(int v) {
    if (v < 0) v = 0;
    if (v >= NN) v = NN - 1;
    return v;
}

// ---------------- init: zero counters + flag + dtype sniff ----------------
__global__ void k_init(const unsigned* __restrict__ w) {
    int i = blockIdx.x * blockDim.x + threadIdx.x;
    if (i < NN) { g_cnt[i] = 0; g_fill[i] = 0; }
    if (i == 0) {
        g_flag = 0;
        int all0 = 1;
        for (int k = 0; k < 64; k++)
            if (w[2 * k + 1] != 0u) { all0 = 0; break; }
        g_is64 = all0;
    }
}

// ---------------- GEMM body (fp16 out) ----------------
template <int CO, int XSEL>
__device__ __forceinline__ void gemm_body(const float* __restrict__ Xext,
                                          const float* __restrict__ W,
                                          __half* __restrict__ H16,
                                          int row0, int c0) {
    const float* X = (XSEL == 0) ? Xext : g_hb;

    __shared__ float Xt[32][130];
    __shared__ __align__(16) float Ws[32][64];

    int tid = threadIdx.x;
    int tx  = tid & 15;
    int ty  = tid >> 4;

    unsigned long long acc[4][4];
    #pragma unroll
    for (int p = 0; p < 4; p++)
        #pragma unroll
        for (int c = 0; c < 4; c++) acc[p][c] = 0ull;

    for (int ch = 0; ch < 4; ch++) {
        #pragma unroll
        for (int it = 0; it < 4; it++) {
            int idx = it * 256 + tid;
            int cc2 = idx & 31;
            int jj  = idx >> 5;
            *(float2*)&Ws[jj][cc2 * 2] =
                *(const float2*)(W + (size_t)(ch * 32 + jj) * CO + c0 + cc2 * 2);
        }
        #pragma unroll
        for (int it = 0; it < 4; it++) {
            int idx = it * 256 + tid;
            int j4  = idx & 7;
            int r   = idx >> 3;
            float4 v = make_float4(0.f, 0.f, 0.f, 0.f);
            if (row0 + r < NN)
                v = *(const float4*)(X + (size_t)(row0 + r) * 128 + ch * 32 + j4 * 4);
            Xt[j4 * 4 + 0][r] = v.x;
            Xt[j4 * 4 + 1][r] = v.y;
            Xt[j4 * 4 + 2][r] = v.z;
            Xt[j4 * 4 + 3][r] = v.w;
        }
        __syncthreads();

        #pragma unroll
        for (int jj = 0; jj < 32; jj++) {
            unsigned long long a[4];
            #pragma unroll
            for (int p = 0; p < 4; p++)
                a[p] = *(const unsigned long long*)&Xt[jj][ty * 8 + p * 2];
            float4 wv = *(const float4*)&Ws[jj][tx * 4];
            unsigned long long wb[4];
            PACK_DUP(wb[0], wv.x);
            PACK_DUP(wb[1], wv.y);
            PACK_DUP(wb[2], wv.z);
            PACK_DUP(wb[3], wv.w);
            #pragma unroll
            for (int c = 0; c < 4; c++)
                #pragma unroll
                for (int p = 0; p < 4; p++)
                    FMA_F32X2(acc[p][c], a[p], wb[c], acc[p][c]);
        }
        __syncthreads();
    }

    #pragma unroll
    for (int p = 0; p < 4; p++) {
        int r = row0 + ty * 8 + p * 2;
        float4 lo, hi;
        float* lop = &lo.x; float* hip = &hi.x;
        #pragma unroll
        for (int c = 0; c < 4; c++) {
            lop[c] = __uint_as_float((unsigned)(acc[p][c] & 0xffffffffull));
            hip[c] = __uint_as_float((unsigned)(acc[p][c] >> 32));
        }
        __half2 l01 = __floats2half2_rn(lo.x, lo.y);
        __half2 l23 = __floats2half2_rn(lo.z, lo.w);
        __half2 h01 = __floats2half2_rn(hi.x, hi.y);
        __half2 h23 = __floats2half2_rn(hi.z, hi.w);
        if (r < NN) {
            uint2 v; v.x = *(unsigned*)&l01; v.y = *(unsigned*)&l23;
            *(uint2*)(H16 + (size_t)r * CO + c0 + tx * 4) = v;
        }
        if (r + 1 < NN) {
            uint2 v; v.x = *(unsigned*)&h01; v.y = *(unsigned*)&h23;
            *(uint2*)(H16 + (size_t)(r + 1) * CO + c0 + tx * 4) = v;
        }
    }
}

// ---------------- fused A: GEMM1 cols 0-63 || edge count ----------------
__global__ __launch_bounds__(256) void k_fusedA(const float* __restrict__ x,
                                                const float* __restrict__ W1,
                                                const void* __restrict__ ei) {
    if (blockIdx.x < GB1) {
        gemm_body<128, 0>(x, W1, g_h1h, blockIdx.x * 128, 0);
    } else {
        int idx = (blockIdx.x - GB1) * 256 + threadIdx.x;
        if (idx < EE / 2) {
            int d0, d1;
            if (g_is64) {
                ulonglong2 p = ((const ulonglong2*)((const char*)ei + (size_t)EE * 8))[idx];
                d0 = clampn((int)p.x); d1 = clampn((int)p.y);
            } else {
                int2 p = ((const int2*)((const char*)ei + (size_t)EE * 4))[idx];
                d0 = clampn(p.x); d1 = clampn(p.y);
            }
            atomicAdd(&g_cnt[d0], 1);
            atomicAdd(&g_cnt[d1], 1);
        }
    }
}

// ---------------- merged scan: block sums + publish/spin + rowptr + dinv ----------------
__global__ __launch_bounds__(1024) void k_scan49() {
    __shared__ int sh[1024];
    __shared__ int sb[64];
    __shared__ int s_boff;
    int t = threadIdx.x;
    int i = blockIdx.x * 1024 + t;
    int c = (i < NN) ? g_cnt[i] : 0;

    // block-local inclusive scan
    sh[t] = c;
    __syncthreads();
    #pragma unroll
    for (int off = 1; off < 1024; off <<= 1) {
        int u = (t >= off) ? sh[t - off] : 0;
        __syncthreads();
        sh[t] += u;
        __syncthreads();
    }

    // publish block sum, then wait for all blocks
    if (t == 1023) {
        g_bsum[blockIdx.x] = sh[1023];
        __threadfence();
        atomicAdd(&g_flag, 1);
    }
    if (t == 0) {
        while (*(volatile int*)&g_flag < NB_SCAN) { }
    }
    __syncthreads();

    // scan the 49 block sums locally
    if (t < 64) sb[t] = (t < NB_SCAN) ? *(volatile int*)&g_bsum[t] : 0;
    __syncthreads();
    #pragma unroll
    for (int off = 1; off < 64; off <<= 1) {
        int u = (t < 64 && t >= off) ? sb[t - off] : 0;
        __syncthreads();
        if (t < 64) sb[t] += u;
        __syncthreads();
    }
    if (t == 0) s_boff = (blockIdx.x == 0) ? 0 : sb[blockIdx.x - 1];
    __syncthreads();

    if (i < NN) {
        g_rowptr[i] = sh[t] - c + s_boff;
        g_dinv[i]   = rsqrtf((float)(c + 1));
    }
    if (i == 0) g_rowptr[NN] = EE;
}

// ---------------- fused B: GEMM1 cols 64-127 || edge scatter ----------------
__global__ __launch_bounds__(256) void k_fusedB(const float* __restrict__ x,
                                                const float* __restrict__ W1,
                                                const void* __restrict__ ei) {
    if (blockIdx.x < GB1) {
        gemm_body<128, 0>(x, W1, g_h1h, blockIdx.x * 128, 64);
    } else {
        int idx = (blockIdx.x - GB1) * 256 + threadIdx.x;
        if (idx < EE / 2) {
            int s0, s1, d0, d1;
            if (g_is64) {
                ulonglong2 ps = ((const ulonglong2*)ei)[idx];
                ulonglong2 pd = ((const ulonglong2*)((const char*)ei + (size_t)EE * 8))[idx];
                s0 = clampn((int)ps.x); s1 = clampn((int)ps.y);
                d0 = clampn((int)pd.x); d1 = clampn((int)pd.y);
            } else {
                int2 ps = ((const int2*)ei)[idx];
                int2 pd = ((const int2*)((const char*)ei + (size_t)EE * 4))[idx];
                s0 = clampn(ps.x); s1 = clampn(ps.y);
                d0 = clampn(pd.x); d1 = clampn(pd.y);
            }
            int p0 = g_rowptr[d0] + atomicAdd(&g_fill[d0], 1);
            g_col[p0] = s0;
            int p1 = g_rowptr[d1] + atomicAdd(&g_fill[d1], 1);
            g_col[p1] = s1;
        }
    }
}

// ---------------- standalone GEMM (layer 2) ----------------
__global__ __launch_bounds__(256) void k_gemm2(const float* __restrict__ W) {
    gemm_body<64, 1>(nullptr, W, g_t2h, blockIdx.x * 128, 0);
}

// ---------------- agg layer 1: warp per node, fp16 gather (C=128), x8 unroll ----------------
__global__ __launch_bounds__(256) void k_agg1(const float* __restrict__ bias) {
    int w    = (blockIdx.x * 256 + threadIdx.x) >> 5;
    int lane = threadIdx.x & 31;
    if (w >= NN) return;
    float di = g_dinv[w];
    float acc0, acc1, acc2, acc3;

    {
        float sn = di * di;
        uint2 raw = *(const uint2*)(g_h1h + (size_t)w * 128 + lane * 4);
        float2 fa = __half22float2(*(__half2*)&raw.x);
        float2 fb = __half22float2(*(__half2*)&raw.y);
        acc0 = fa.x * sn; acc1 = fa.y * sn; acc2 = fb.x * sn; acc3 = fb.y * sn;
    }

    int beg = g_rowptr[w];
    int end = g_rowptr[w + 1];
    int j   = beg;

    for (; j + 8 <= end; j += 8) {
        int   si[8];
        float ni[8];
        #pragma unroll
        for (int q = 0; q < 8; q++) si[q] = g_col[j + q];
        #pragma unroll
        for (int q = 0; q < 8; q++) ni[q] = g_dinv[si[q]] * di;
        uint2 rv[8];
        #pragma unroll
        for (int q = 0; q < 8; q++)
            rv[q] = *(const uint2*)(g_h1h + (size_t)si[q] * 128 + lane * 4);
        #pragma unroll
        for (int q = 0; q < 8; q++) {
            float2 fa = __half22float2(*(__half2*)&rv[q].x);
            float2 fb = __half22float2(*(__half2*)&rv[q].y);
            acc0 += fa.x * ni[q]; acc1 += fa.y * ni[q];
            acc2 += fb.x * ni[q]; acc3 += fb.y * ni[q];
        }
    }
    if (j + 4 <= end) {
        int   si[4];
        float ni[4];
        #pragma unroll
        for (int q = 0; q < 4; q++) si[q] = g_col[j + q];
        #pragma unroll
        for (int q = 0; q < 4; q++) ni[q] = g_dinv[si[q]] * di;
        uint2 rv[4];
        #pragma unroll
        for (int q = 0; q < 4; q++)
            rv[q] = *(const uint2*)(g_h1h + (size_t)si[q] * 128 + lane * 4);
        #pragma unroll
        for (int q = 0; q < 4; q++) {
            float2 fa = __half22float2(*(__half2*)&rv[q].x);
            float2 fb = __half22float2(*(__half2*)&rv[q].y);
            acc0 += fa.x * ni[q]; acc1 += fa.y * ni[q];
            acc2 += fb.x * ni[q]; acc3 += fb.y * ni[q];
        }
        j += 4;
    }
    for (; j < end; j++) {
        int   s   = g_col[j];
        float nrm = g_dinv[s] * di;
        uint2 raw = *(const uint2*)(g_h1h + (size_t)s * 128 + lane * 4);
        float2 fa = __half22float2(*(__half2*)&raw.x);
        float2 fb = __half22float2(*(__half2*)&raw.y);
        acc0 += fa.x * nrm; acc1 += fa.y * nrm; acc2 += fb.x * nrm; acc3 += fb.y * nrm;
    }

    float4 r;
    r.x = fmaxf(acc0 + bias[lane * 4 + 0], 0.f);
    r.y = fmaxf(acc1 + bias[lane * 4 + 1], 0.f);
    r.z = fmaxf(acc2 + bias[lane * 4 + 2], 0.f);
    r.w = fmaxf(acc3 + bias[lane * 4 + 3], 0.f);
    *(float4*)(g_hb + (size_t)w * 128 + lane * 4) = r;
}

// ---------------- agg layer 2: warp per node, fp16 gather (C=64), x8 unroll ----------------
__global__ __launch_bounds__(256) void k_agg2(const float* __restrict__ bias,
                                              float* __restrict__ out) {
    int w    = (blockIdx.x * 256 + threadIdx.x) >> 5;
    int lane = threadIdx.x & 31;
    if (w >= NN) return;
    float di = g_dinv[w];
    float acc0, acc1;

    {
        float sn = di * di;
        unsigned raw = *(const unsigned*)(g_t2h + (size_t)w * 64 + lane * 2);
        float2 v = __half22float2(*(__half2*)&raw);
        acc0 = v.x * sn; acc1 = v.y * sn;
    }

    int beg = g_rowptr[w];
    int end = g_rowptr[w + 1];
    int j   = beg;

    for (; j + 8 <= end; j += 8) {
        int   si[8];
        float ni[8];
        #pragma unroll
        for (int q = 0; q < 8; q++) si[q] = g_col[j + q];
        #pragma unroll
        for (int q = 0; q < 8; q++) ni[q] = g_dinv[si[q]] * di;
        unsigned rv[8];
        #pragma unroll
        for (int q = 0; q < 8; q++)
            rv[q] = *(const unsigned*)(g_t2h + (size_t)si[q] * 64 + lane * 2);
        #pragma unroll
        for (int q = 0; q < 8; q++) {
            float2 v = __half22float2(*(__half2*)&rv[q]);
            acc0 += v.x * ni[q]; acc1 += v.y * ni[q];
        }
    }
    if (j + 4 <= end) {
        int   si[4];
        float ni[4];
        #pragma unroll
        for (int q = 0; q < 4; q++) si[q] = g_col[j + q];
        #pragma unroll
        for (int q = 0; q < 4; q++) ni[q] = g_dinv[si[q]] * di;
        unsigned rv[4];
        #pragma unroll
        for (int q = 0; q < 4; q++)
            rv[q] = *(const unsigned*)(g_t2h + (size_t)si[q] * 64 + lane * 2);
        #pragma unroll
        for (int q = 0; q < 4; q++) {
            float2 v = __half22float2(*(__half2*)&rv[q]);
            acc0 += v.x * ni[q]; acc1 += v.y * ni[q];
        }
        j += 4;
    }
    for (; j < end; j++) {
        int   s   = g_col[j];
        float nrm = g_dinv[s] * di;
        unsigned raw = *(const unsigned*)(g_t2h + (size_t)s * 64 + lane * 2);
        float2 v = __half22float2(*(__half2*)&raw);
        acc0 += v.x * nrm; acc1 += v.y * nrm;
    }

    float2 r;
    r.x = acc0 + bias[lane * 2 + 0];
    r.y = acc1 + bias[lane * 2 + 1];
    *(float2*)(out + (size_t)w * 64 + lane * 2) = r;
}

// ---------------- launch ----------------
extern "C" void kernel_launch(void* const* d_in, const int* in_sizes, int n_in,
                              void* d_out, int out_size) {
    const float* x   = (const float*)d_in[0];
    const void*  ei  = d_in[1];
    const float* W1  = (const float*)d_in[2];
    const float* b1  = (const float*)d_in[3];
    const float* W2  = (const float*)d_in[4];
    const float* b2  = (const float*)d_in[5];
    float*       out = (float*)d_out;

    k_init<<<(NN + 255) / 256, 256>>>((const unsigned*)ei);
    k_fusedA<<<GB1 + EB2, 256>>>(x, W1, ei);   // gemm1 half0 || count
    k_scan49<<<NB_SCAN, 1024>>>();             // merged bsum + rowptr
    k_fusedB<<<GB1 + EB2, 256>>>(x, W1, ei);   // gemm1 half1 || scatter

    k_agg1<<<(NN * 32 + 255) / 256, 256>>>(b1);
    k_gemm2<<<GB1, 256>>>(W2);
    k_agg2<<<(NN * 32 + 255) / 256, 256>>>(b2, out);
}